// round 13
// baseline (speedup 1.0000x reference)
#include <cuda_runtime.h>
#include <cuda_fp16.h>
#include <cstdint>

// Problem constants
#define B_ 64
#define T_ 1024
#define E_ 128
#define F_ 64
#define C_ 5
#define TILE_T 64
#define XROWS (TILE_T + C_ - 1)   // 68

// smem (dynamic): bias + two A windows (A0 reused as fp32 transpose buffer)
#define SM_BIAS 0                        // 64 floats (256B)
#define SM_A0   1024                     // 68 rows x 256B = 17408
#define SM_A1   (SM_A0 + 17408)
#define SM_TOTAL (SM_A1 + 17408)         // 35840 bytes

// W pre-permuted into mma B-fragment layout:
// uint32 index = (((c*8+ks)*4 + p)*32 + lane)*4 + comp,
//   tile = 2p + (comp>>1), j = comp&1
//   value = half2( W[tile*8 + lane/4][c*128+ks*16+2*(lane%4)+8j], [..+1] )
__device__ __align__(16) uint32_t g_Wfrag[C_ * 8 * 4 * 32 * 4];   // 81920 B

static __device__ __forceinline__ uint32_t smem_u32(const void* p) {
    uint32_t a;
    asm("{ .reg .u64 t; cvta.to.shared.u64 t, %1; cvt.u32.u64 %0, t; }" : "=r"(a) : "l"(p));
    return a;
}
static __device__ __forceinline__ void ldsm4(uint32_t r[4], uint32_t addr) {
    asm volatile("ldmatrix.sync.aligned.m8n8.x4.shared.b16 {%0,%1,%2,%3}, [%4];"
                 : "=r"(r[0]), "=r"(r[1]), "=r"(r[2]), "=r"(r[3]) : "r"(addr));
}
static __device__ __forceinline__ void mma_fp16(float (&d)[4], const uint32_t a[4],
                                                uint32_t b0, uint32_t b1) {
    asm volatile(
        "mma.sync.aligned.m16n8k16.row.col.f32.f16.f16.f32 "
        "{%0,%1,%2,%3}, {%4,%5,%6,%7}, {%8,%9}, {%0,%1,%2,%3};"
        : "+f"(d[0]), "+f"(d[1]), "+f"(d[2]), "+f"(d[3])
        : "r"(a[0]), "r"(a[1]), "r"(a[2]), "r"(a[3]), "r"(b0), "r"(b1));
}

// Setup: W fp32 -> fragment-major fp16 (once per launch)
__global__ void convert_w_frag_kernel(const float* __restrict__ W) {
    int idx = blockIdx.x * 256 + threadIdx.x;        // uint32 index
    if (idx >= C_ * 8 * 4 * 32 * 4) return;
    int comp = idx & 3;
    int l    = (idx >> 2) & 31;
    int p    = (idx >> 7) & 3;
    int s    = idx >> 9;                 // c*8 + ks, 0..39
    int c    = s >> 3;
    int ks   = s & 7;
    int tile = 2 * p + (comp >> 1);
    int j    = comp & 1;
    int f    = tile * 8 + (l >> 2);
    int kk   = c * E_ + ks * 16 + 2 * (l & 3) + 8 * j;
    const float* wr = W + (size_t)f * (C_ * E_) + kk;
    __half2 h = __floats2half2_rn(wr[0], wr[1]);
    g_Wfrag[idx] = *(uint32_t*)&h;
}

__global__ __launch_bounds__(128, 5)
void qa_cnn_hmma_kernel(const float* __restrict__ x,
                        const float* __restrict__ bias,
                        float* __restrict__ out)
{
    extern __shared__ char smc[];
    const uint32_t sbase = smem_u32(smc);
    const int tid = threadIdx.x;
    const int wid = tid >> 5;
    const int lid = tid & 31;
    const int b   = blockIdx.y;
    const int t0  = blockIdx.x * (2 * TILE_T);   // pair base: tiles at t0 and t0+64

    float* bias_s = (float*)(smc + SM_BIAS);
    if (tid < F_) bias_s[tid] = bias[tid];

    const float* xb = x + (size_t)b * T_ * E_;

    // ---- stage tile0 window: x[b, t0-2 .. t0+65] -> fp16 in A0 ----
#pragma unroll
    for (int it = 0; it < 17; ++it) {
        int idx = tid + it * 128;
        int row = idx >> 5;
        int e4  = (idx & 31) << 2;
        int t   = t0 - 2 + row;
        float4 v = make_float4(0.f, 0.f, 0.f, 0.f);
        if (t >= 0 && t < T_) v = *(const float4*)(xb + (size_t)t * E_ + e4);
        __half2 p0 = __floats2half2_rn(v.x, v.y);
        __half2 p1 = __floats2half2_rn(v.z, v.w);
        uint32_t off = (uint32_t)row * 256u +
                       (((uint32_t)(e4 << 1)) ^ (((uint32_t)row & 7u) << 4));
        *(uint2*)(smc + SM_A0 + off) = make_uint2(*(uint32_t*)&p0, *(uint32_t*)&p1);
    }
    __syncthreads();

    // Warp tiling: warp_m 0..1 (32 tokens), warp_f 0..1 (32 filters)
    const int warp_m = wid & 1;
    const int warp_f = wid >> 1;
    const int arow   = lid & 15;
    const int achalf = lid >> 4;
    const int row_w0 = warp_m * 32 + arow;

    const uint4* gw = (const uint4*)g_Wfrag + (size_t)(warp_f * 2) * 32 + lid;

    // prefetch chunk row/col for this thread (same for all chunks modulo +128 idx)
    float4 pf[4];                        // chunk slots (rotating)

    uint32_t abuf[2][2][4];
    uint4    wbuf[2][2];

#define LOAD_STEP(s, slot, abase)                                                \
    {                                                                            \
        int c_  = (s) >> 3;                                                      \
        int ks_ = (s) & 7;                                                       \
        uint32_t swz_  = (((uint32_t)(row_w0 + c_)) & 7u) << 4;                  \
        uint32_t aoff_ = ((uint32_t)(ks_ * 32) + (uint32_t)(achalf * 16)) ^ swz_;\
        uint32_t ab_   = (abase) + (uint32_t)(c_ * 256);                         \
        ldsm4(abuf[slot][0], ab_ + aoff_);                                       \
        ldsm4(abuf[slot][1], ab_ + 4096u + aoff_);                               \
        wbuf[slot][0] = gw[(size_t)((s) * 4)     * 32];                          \
        wbuf[slot][1] = gw[(size_t)((s) * 4 + 1) * 32];                          \
    }

#pragma unroll
    for (int g = 0; g < 2; ++g) {
        const uint32_t a_base0 = sbase + (g ? SM_A1 : SM_A0) + (uint32_t)row_w0 * 256u;

        float acc[2][4][4];
#pragma unroll
        for (int m = 0; m < 2; ++m)
#pragma unroll
            for (int q = 0; q < 4; ++q)
#pragma unroll
                for (int r = 0; r < 4; ++r) acc[m][q][r] = 0.f;

        LOAD_STEP(0, 0, a_base0)
        LOAD_STEP(1, 1, a_base0)

#pragma unroll
        for (int s = 0; s < 40; ++s) {
            const int cur = s & 1;
#pragma unroll
            for (int m = 0; m < 2; ++m) {
                const uint32_t* am = abuf[cur][m];
                mma_fp16(acc[m][0], am, wbuf[cur][0].x, wbuf[cur][0].y);
                mma_fp16(acc[m][1], am, wbuf[cur][0].z, wbuf[cur][0].w);
                mma_fp16(acc[m][2], am, wbuf[cur][1].x, wbuf[cur][1].y);
                mma_fp16(acc[m][3], am, wbuf[cur][1].z, wbuf[cur][1].w);
            }
            if (s + 2 < 40) { LOAD_STEP(s + 2, cur, a_base0) }

            if (g == 0) {
                // ---- interleaved prefetch of tile1 window into A1 ----
                if ((s & 1) == 0 && (s >> 1) < 17) {
                    const int i = s >> 1;            // chunk 0..16, issue LDG
                    int idx = tid + i * 128;
                    int row = idx >> 5;
                    int e4  = (idx & 31) << 2;
                    int t   = t0 + TILE_T - 2 + row;
                    float4 v = make_float4(0.f, 0.f, 0.f, 0.f);
                    if (t >= 0 && t < T_) v = *(const float4*)(xb + (size_t)t * E_ + e4);
                    pf[i & 3] = v;
                }
                if ((s & 1) == 1 && s >= 7 && ((s - 7) >> 1) < 17) {
                    const int i = (s - 7) >> 1;      // chunk 0..16, convert+STS
                    int idx = tid + i * 128;
                    int row = idx >> 5;
                    int e4  = (idx & 31) << 2;
                    float4 v = pf[i & 3];
                    __half2 p0 = __floats2half2_rn(v.x, v.y);
                    __half2 p1 = __floats2half2_rn(v.z, v.w);
                    uint32_t off = (uint32_t)row * 256u +
                                   (((uint32_t)(e4 << 1)) ^ (((uint32_t)row & 7u) << 4));
                    *(uint2*)(smc + SM_A1 + off) = make_uint2(*(uint32_t*)&p0, *(uint32_t*)&p1);
                }
            }
        }

        // ---- epilogue tile g: transpose through A0 region, coalesced stores ----
        __syncthreads();   // mainloop LDSM done; tile1 STS complete; so-buffer free
        float* so = (float*)(smc + SM_A0);   // so[f*66 + t], 64 x 66 floats

        const int t_base = warp_m * 32 + (lid >> 2);
        const int f_base = warp_f * 32 + (lid & 3) * 2;
#pragma unroll
        for (int m = 0; m < 2; ++m) {
#pragma unroll
            for (int q = 0; q < 4; ++q) {
                int f = f_base + q * 8;
                int t = t_base + m * 16;
                so[f * 66 + t]           = acc[m][q][0];
                so[(f + 1) * 66 + t]     = acc[m][q][1];
                so[f * 66 + t + 8]       = acc[m][q][2];
                so[(f + 1) * 66 + t + 8] = acc[m][q][3];
            }
        }
        __syncthreads();

        float* ob = out + (size_t)b * F_ * T_ + t0 + g * TILE_T;
#pragma unroll
        for (int k = 0; k < 16; ++k) {
            int f = wid * 16 + k;
            float bb = bias_s[f];
            __stcs(ob + (size_t)f * T_ + lid,      so[f * 66 + lid] + bb);
            __stcs(ob + (size_t)f * T_ + 32 + lid, so[f * 66 + 32 + lid] + bb);
        }
    }
#undef LOAD_STEP
}

extern "C" void kernel_launch(void* const* d_in, const int* in_sizes, int n_in,
                              void* d_out, int out_size)
{
    const float* x    = (const float*)d_in[0];  // [B, T, E]
    const float* W    = (const float*)d_in[1];  // [F, C*E]
    const float* bias = (const float*)d_in[2];  // [F]
    float* out = (float*)d_out;                 // [B, F, T]

    convert_w_frag_kernel<<<(C_ * 8 * 4 * 32 * 4 + 255) / 256, 256>>>(W);

    cudaFuncSetAttribute(qa_cnn_hmma_kernel,
                         cudaFuncAttributeMaxDynamicSharedMemorySize, SM_TOTAL);
    dim3 grid(T_ / (2 * TILE_T), B_);   // 8 x 64 = 512 CTAs, 2 tiles each
    qa_cnn_hmma_kernel<<<grid, 128, SM_TOTAL>>>(x, bias, out);
}

// round 14
// speedup vs baseline: 1.0026x; 1.0026x over previous
#include <cuda_runtime.h>
#include <cuda_fp16.h>
#include <cstdint>

// Problem constants
#define B_ 64
#define T_ 1024
#define E_ 128
#define F_ 64
#define C_ 5
#define TILE_T 32
#define XROWS (TILE_T + C_ - 1)   // 36

// smem (dynamic): bias + A window (reused as fp32 transpose buffer, 64x36 floats)
#define SM_BIAS 0                        // 64 floats (256B)
#define SM_A    1024                     // 36 rows x 256B = 9216 (= 64*36*4 exactly)
#define SM_TOTAL (SM_A + XROWS * 256)    // 10240 bytes -> 8 CTAs/SM (reg-limited)

// W pre-permuted into mma B-fragment layout:
// uint32 index = (((c*8+ks)*4 + p)*32 + lane)*4 + comp,
//   tile = 2p + (comp>>1), j = comp&1
//   value = half2( W[tile*8 + lane/4][c*128+ks*16+2*(lane%4)+8j], [..+1] )
__device__ __align__(16) uint32_t g_Wfrag[C_ * 8 * 4 * 32 * 4];   // 81920 B

static __device__ __forceinline__ uint32_t smem_u32(const void* p) {
    uint32_t a;
    asm("{ .reg .u64 t; cvta.to.shared.u64 t, %1; cvt.u32.u64 %0, t; }" : "=r"(a) : "l"(p));
    return a;
}
static __device__ __forceinline__ void ldsm4(uint32_t r[4], uint32_t addr) {
    asm volatile("ldmatrix.sync.aligned.m8n8.x4.shared.b16 {%0,%1,%2,%3}, [%4];"
                 : "=r"(r[0]), "=r"(r[1]), "=r"(r[2]), "=r"(r[3]) : "r"(addr));
}
static __device__ __forceinline__ void mma_fp16(float (&d)[4], const uint32_t a[4],
                                                uint32_t b0, uint32_t b1) {
    asm volatile(
        "mma.sync.aligned.m16n8k16.row.col.f32.f16.f16.f32 "
        "{%0,%1,%2,%3}, {%4,%5,%6,%7}, {%8,%9}, {%0,%1,%2,%3};"
        : "+f"(d[0]), "+f"(d[1]), "+f"(d[2]), "+f"(d[3])
        : "r"(a[0]), "r"(a[1]), "r"(a[2]), "r"(a[3]), "r"(b0), "r"(b1));
}

// Setup: W fp32 -> fragment-major fp16 (once per launch)
__global__ void convert_w_frag_kernel(const float* __restrict__ W) {
    int idx = blockIdx.x * 256 + threadIdx.x;        // uint32 index
    if (idx >= C_ * 8 * 4 * 32 * 4) return;
    int comp = idx & 3;
    int l    = (idx >> 2) & 31;
    int p    = (idx >> 7) & 3;
    int s    = idx >> 9;                 // c*8 + ks, 0..39
    int c    = s >> 3;
    int ks   = s & 7;
    int tile = 2 * p + (comp >> 1);
    int j    = comp & 1;
    int f    = tile * 8 + (l >> 2);
    int kk   = c * E_ + ks * 16 + 2 * (l & 3) + 8 * j;
    const float* wr = W + (size_t)f * (C_ * E_) + kk;
    __half2 h = __floats2half2_rn(wr[0], wr[1]);
    g_Wfrag[idx] = *(uint32_t*)&h;
}

__global__ __launch_bounds__(128, 8)
void qa_cnn_hmma_kernel(const float* __restrict__ x,
                        const float* __restrict__ bias,
                        float* __restrict__ out)
{
    extern __shared__ char smc[];
    const uint32_t sbase = smem_u32(smc);
    const int tid = threadIdx.x;
    const int wid = tid >> 5;
    const int lid = tid & 31;
    const int b   = blockIdx.y;
    const int t0  = blockIdx.x * TILE_T;

    float* bias_s = (float*)(smc + SM_BIAS);
    if (tid < F_) bias_s[tid] = bias[tid];

    // ---- stage A window: x[b, t0-2 .. t0+33], 36 x 128 fp32 -> fp16 ----
    const float* xb = x + (size_t)b * T_ * E_;
#pragma unroll
    for (int it = 0; it < 9; ++it) {         // 36*32 = 1152 float4 chunks
        int idx = tid + it * 128;
        int row = idx >> 5;
        int e4  = (idx & 31) << 2;
        int t   = t0 - 2 + row;
        float4 v = make_float4(0.f, 0.f, 0.f, 0.f);
        if (t >= 0 && t < T_) v = *(const float4*)(xb + (size_t)t * E_ + e4);
        __half2 p0 = __floats2half2_rn(v.x, v.y);
        __half2 p1 = __floats2half2_rn(v.z, v.w);
        uint32_t off = (uint32_t)row * 256u +
                       (((uint32_t)(e4 << 1)) ^ (((uint32_t)row & 7u) << 4));
        *(uint2*)(smc + SM_A + off) = make_uint2(*(uint32_t*)&p0, *(uint32_t*)&p1);
    }
    __syncthreads();

    // Warp tiling: warp_m 0..1 (16 tokens each), warp_f 0..1 (32 filters each)
    const int warp_m = wid & 1;
    const int warp_f = wid >> 1;
    const int arow   = lid & 15;
    const int achalf = lid >> 4;
    const int row_w0 = warp_m * 16 + arow;
    const uint32_t a_base0 = sbase + SM_A + (uint32_t)row_w0 * 256u;

    // B fragment pointer: uint4 index = (s*4 + warp_f*2 + pl)*32 + lid
    const uint4* gw = (const uint4*)g_Wfrag + (size_t)(warp_f * 2) * 32 + lid;

    float acc[4][4];
#pragma unroll
    for (int q = 0; q < 4; ++q)
#pragma unroll
        for (int r = 0; r < 4; ++r) acc[q][r] = 0.f;

    // Depth-2 pipeline, 2 buffers: consume slot at step s, reload for s+2.
    uint32_t abuf[2][4];      // [slot][reg]  (one m16 tile)
    uint4    wbuf[2][2];      // [slot][pl]

#define LOAD_STEP(s, slot)                                                       \
    {                                                                            \
        int c_  = (s) >> 3;                                                      \
        int ks_ = (s) & 7;                                                       \
        uint32_t swz_  = (((uint32_t)(row_w0 + c_)) & 7u) << 4;                  \
        uint32_t aoff_ = ((uint32_t)(ks_ * 32) + (uint32_t)(achalf * 16)) ^ swz_;\
        ldsm4(abuf[slot], a_base0 + (uint32_t)(c_ * 256) + aoff_);               \
        wbuf[slot][0] = gw[(size_t)((s) * 4)     * 32];                          \
        wbuf[slot][1] = gw[(size_t)((s) * 4 + 1) * 32];                          \
    }

    LOAD_STEP(0, 0)
    LOAD_STEP(1, 1)

#pragma unroll
    for (int s = 0; s < 40; ++s) {
        const int cur = s & 1;
        mma_fp16(acc[0], abuf[cur], wbuf[cur][0].x, wbuf[cur][0].y);
        mma_fp16(acc[1], abuf[cur], wbuf[cur][0].z, wbuf[cur][0].w);
        mma_fp16(acc[2], abuf[cur], wbuf[cur][1].x, wbuf[cur][1].y);
        mma_fp16(acc[3], abuf[cur], wbuf[cur][1].z, wbuf[cur][1].w);
        if (s + 2 < 40) { LOAD_STEP(s + 2, cur) }
    }
#undef LOAD_STEP

    // ---- epilogue: transpose through smem (stride 36: bank-perfect), store ----
    __syncthreads();   // all LDSM from SM_A done; safe to overwrite
    float* so = (float*)(smc + SM_A);    // so[f*36 + t], 64 x 36 floats (9216B)

    const int t_base = warp_m * 16 + (lid >> 2);
    const int f_base = warp_f * 32 + (lid & 3) * 2;
#pragma unroll
    for (int q = 0; q < 4; ++q) {
        int f = f_base + q * 8;
        so[f * 36 + t_base]           = acc[q][0];
        so[(f + 1) * 36 + t_base]     = acc[q][1];
        so[f * 36 + t_base + 8]       = acc[q][2];
        so[(f + 1) * 36 + t_base + 8] = acc[q][3];
    }
    __syncthreads();

    float* ob = out + (size_t)b * F_ * T_ + t0;
#pragma unroll
    for (int k = 0; k < 16; ++k) {
        int f = wid * 16 + k;
        __stcs(ob + (size_t)f * T_ + lid, so[f * 36 + lid] + bias_s[f]);
    }
}

extern "C" void kernel_launch(void* const* d_in, const int* in_sizes, int n_in,
                              void* d_out, int out_size)
{
    const float* x    = (const float*)d_in[0];  // [B, T, E]
    const float* W    = (const float*)d_in[1];  // [F, C*E]
    const float* bias = (const float*)d_in[2];  // [F]
    float* out = (float*)d_out;                 // [B, F, T]

    convert_w_frag_kernel<<<(C_ * 8 * 4 * 32 * 4 + 255) / 256, 256>>>(W);

    cudaFuncSetAttribute(qa_cnn_hmma_kernel,
                         cudaFuncAttributeMaxDynamicSharedMemorySize, SM_TOTAL);
    dim3 grid(T_ / TILE_T, B_);   // 32 x 64 = 2048 CTAs, 8 CTAs/SM
    qa_cnn_hmma_kernel<<<grid, 128, SM_TOTAL>>>(x, bias, out);
}

// round 15
// speedup vs baseline: 1.1496x; 1.1466x over previous
#include <cuda_runtime.h>
#include <cuda_fp16.h>
#include <cstdint>

// Problem constants
#define B_ 64
#define T_ 1024
#define E_ 128
#define F_ 64
#define C_ 5
#define TILE_T 64
#define XROWS (TILE_T + C_ - 1)   // 68

// smem (dynamic): bias + A window (A region reused as fp32 transpose buffer)
#define SM_BIAS 0                        // 64 floats (256B)
#define SM_A    1024                     // 68 rows x 256B = 17408 (>= 64*66*4 = 16896)
#define SM_TOTAL (SM_A + XROWS * 256)    // 18432 bytes -> 7 CTAs/SM needs 129KB < 228KB ok

// W pre-permuted into mma B-fragment layout:
// uint32 index = (((c*8+ks)*4 + p)*32 + lane)*4 + comp,
//   tile = 2p + (comp>>1), j = comp&1
//   value = half2( W[tile*8 + lane/4][c*128+ks*16+2*(lane%4)+8j], [..+1] )
__device__ __align__(16) uint32_t g_Wfrag[C_ * 8 * 4 * 32 * 4];   // 81920 B

static __device__ __forceinline__ uint32_t smem_u32(const void* p) {
    uint32_t a;
    asm("{ .reg .u64 t; cvta.to.shared.u64 t, %1; cvt.u32.u64 %0, t; }" : "=r"(a) : "l"(p));
    return a;
}
static __device__ __forceinline__ void ldsm4(uint32_t r[4], uint32_t addr) {
    asm volatile("ldmatrix.sync.aligned.m8n8.x4.shared.b16 {%0,%1,%2,%3}, [%4];"
                 : "=r"(r[0]), "=r"(r[1]), "=r"(r[2]), "=r"(r[3]) : "r"(addr));
}
static __device__ __forceinline__ void mma_fp16(float (&d)[4], const uint32_t a[4],
                                                uint32_t b0, uint32_t b1) {
    asm volatile(
        "mma.sync.aligned.m16n8k16.row.col.f32.f16.f16.f32 "
        "{%0,%1,%2,%3}, {%4,%5,%6,%7}, {%8,%9}, {%0,%1,%2,%3};"
        : "+f"(d[0]), "+f"(d[1]), "+f"(d[2]), "+f"(d[3])
        : "r"(a[0]), "r"(a[1]), "r"(a[2]), "r"(a[3]), "r"(b0), "r"(b1));
}

// Setup: W fp32 -> fragment-major fp16 (once per launch)
__global__ void convert_w_frag_kernel(const float* __restrict__ W) {
    int idx = blockIdx.x * 256 + threadIdx.x;        // uint32 index
    if (idx >= C_ * 8 * 4 * 32 * 4) return;
    int comp = idx & 3;
    int l    = (idx >> 2) & 31;
    int p    = (idx >> 7) & 3;
    int s    = idx >> 9;                 // c*8 + ks, 0..39
    int c    = s >> 3;
    int ks   = s & 7;
    int tile = 2 * p + (comp >> 1);
    int j    = comp & 1;
    int f    = tile * 8 + (l >> 2);
    int kk   = c * E_ + ks * 16 + 2 * (l & 3) + 8 * j;
    const float* wr = W + (size_t)f * (C_ * E_) + kk;
    __half2 h = __floats2half2_rn(wr[0], wr[1]);
    g_Wfrag[idx] = *(uint32_t*)&h;
}

__global__ __launch_bounds__(128, 7)
void qa_cnn_hmma_kernel(const float* __restrict__ x,
                        const float* __restrict__ bias,
                        float* __restrict__ out)
{
    extern __shared__ char smc[];
    const uint32_t sbase = smem_u32(smc);
    const int tid = threadIdx.x;
    const int wid = tid >> 5;
    const int lid = tid & 31;
    const int b   = blockIdx.y;
    const int t0  = blockIdx.x * TILE_T;

    float* bias_s = (float*)(smc + SM_BIAS);
    if (tid < F_) bias_s[tid] = bias[tid];

    // ---- stage A window once: x[b, t0-2 .. t0+65], 68 x 128 fp32 -> fp16 ----
    const float* xb = x + (size_t)b * T_ * E_;
#pragma unroll
    for (int it = 0; it < 17; ++it) {
        int idx = tid + it * 128;
        int row = idx >> 5;
        int e4  = (idx & 31) << 2;
        int t   = t0 - 2 + row;
        float4 v = make_float4(0.f, 0.f, 0.f, 0.f);
        if (t >= 0 && t < T_) v = *(const float4*)(xb + (size_t)t * E_ + e4);
        __half2 p0 = __floats2half2_rn(v.x, v.y);
        __half2 p1 = __floats2half2_rn(v.z, v.w);
        uint32_t off = (uint32_t)row * 256u +
                       (((uint32_t)(e4 << 1)) ^ (((uint32_t)row & 7u) << 4));
        *(uint2*)(smc + SM_A + off) = make_uint2(*(uint32_t*)&p0, *(uint32_t*)&p1);
    }
    __syncthreads();

    // Warp tiling: warp_m 0..1 (32 tokens), warp_f 0..1 (32 filters)
    const int warp_m = wid & 1;
    const int warp_f = wid >> 1;
    const int arow   = lid & 15;
    const int achalf = lid >> 4;
    const int row_w0 = warp_m * 32 + arow;
    const uint32_t a_base0 = sbase + SM_A + (uint32_t)row_w0 * 256u;

    // B fragment pointer: uint4 index = (s*4 + warp_f*2 + pl)*32 + lid
    const uint4* gw = (const uint4*)g_Wfrag + (size_t)(warp_f * 2) * 32 + lid;

    float acc[2][4][4];
#pragma unroll
    for (int m = 0; m < 2; ++m)
#pragma unroll
        for (int q = 0; q < 4; ++q)
#pragma unroll
            for (int r = 0; r < 4; ++r) acc[m][q][r] = 0.f;

    // A: depth-2 prefetch (2 slots). W: depth-1 (single buffer) to save 8 regs.
    uint32_t abuf[2][2][4];   // [slot][mtile][reg]
    uint4    wcur[2];         // current step W fragments

#define LOAD_A(s, slot)                                                          \
    {                                                                            \
        int c_  = (s) >> 3;                                                      \
        int ks_ = (s) & 7;                                                       \
        uint32_t swz_  = (((uint32_t)(row_w0 + c_)) & 7u) << 4;                  \
        uint32_t aoff_ = ((uint32_t)(ks_ * 32) + (uint32_t)(achalf * 16)) ^ swz_;\
        uint32_t ab_   = a_base0 + (uint32_t)(c_ * 256);                         \
        ldsm4(abuf[slot][0], ab_ + aoff_);                                       \
        ldsm4(abuf[slot][1], ab_ + 4096u + aoff_);                               \
    }

    LOAD_A(0, 0)
    LOAD_A(1, 1)
    wcur[0] = gw[0];
    wcur[1] = gw[32];

#pragma unroll
    for (int s = 0; s < 40; ++s) {
        const int cur = s & 1;
        uint4 w0 = wcur[0];
        uint4 w1 = wcur[1];
        // prefetch W for step s+1 while consuming current fragments
        if (s + 1 < 40) {
            wcur[0] = gw[(size_t)((s + 1) * 4)     * 32];
            wcur[1] = gw[(size_t)((s + 1) * 4 + 1) * 32];
        }
#pragma unroll
        for (int m = 0; m < 2; ++m) {
            const uint32_t* am = abuf[cur][m];
            mma_fp16(acc[m][0], am, w0.x, w0.y);
            mma_fp16(acc[m][1], am, w0.z, w0.w);
            mma_fp16(acc[m][2], am, w1.x, w1.y);
            mma_fp16(acc[m][3], am, w1.z, w1.w);
        }
        if (s + 2 < 40) { LOAD_A(s + 2, cur) }
    }
#undef LOAD_A

    // ---- epilogue: transpose through smem, then coalesced streaming stores ----
    __syncthreads();   // all LDSM from SM_A done; safe to overwrite
    float* so = (float*)(smc + SM_A);    // so[f*66 + t], 64x66 floats

    const int t_base = warp_m * 32 + (lid >> 2);
    const int f_base = warp_f * 32 + (lid & 3) * 2;
#pragma unroll
    for (int m = 0; m < 2; ++m) {
#pragma unroll
        for (int q = 0; q < 4; ++q) {
            int f = f_base + q * 8;
            int t = t_base + m * 16;
            so[f * 66 + t]           = acc[m][q][0];
            so[(f + 1) * 66 + t]     = acc[m][q][1];
            so[f * 66 + t + 8]       = acc[m][q][2];
            so[(f + 1) * 66 + t + 8] = acc[m][q][3];
        }
    }
    __syncthreads();

    float* ob = out + (size_t)b * F_ * T_ + t0;
#pragma unroll
    for (int k = 0; k < 16; ++k) {
        int f = wid * 16 + k;
        float bb = bias_s[f];
        __stcs(ob + (size_t)f * T_ + lid,      so[f * 66 + lid] + bb);
        __stcs(ob + (size_t)f * T_ + 32 + lid, so[f * 66 + 32 + lid] + bb);
    }
}

extern "C" void kernel_launch(void* const* d_in, const int* in_sizes, int n_in,
                              void* d_out, int out_size)
{
    const float* x    = (const float*)d_in[0];  // [B, T, E]
    const float* W    = (const float*)d_in[1];  // [F, C*E]
    const float* bias = (const float*)d_in[2];  // [F]
    float* out = (float*)d_out;                 // [B, F, T]

    convert_w_frag_kernel<<<(C_ * 8 * 4 * 32 * 4 + 255) / 256, 256>>>(W);

    cudaFuncSetAttribute(qa_cnn_hmma_kernel,
                         cudaFuncAttributeMaxDynamicSharedMemorySize, SM_TOTAL);
    dim3 grid(T_ / TILE_T, B_);   // 16 x 64 = 1024 CTAs, 7 CTAs/SM
    qa_cnn_hmma_kernel<<<grid, 128, SM_TOTAL>>>(x, bias, out);
}